// round 4
// baseline (speedup 1.0000x reference)
#include <cuda_runtime.h>
#include <cuda_bf16.h>
#include <cstdint>

// Problem constants
#define BB   64      // batch
#define CIN  64
#define COUT 128
#define HH   1855
#define KK   6
#define KT   7            // center + 6 neighbors
#define KDIM (KT * CIN)   // 448

// Scratch (device globals; no allocation allowed)
__device__ float g_xT[(size_t)HH * CIN * BB];   // [h][c][b]  ~30.4 MB
__device__ float g_Wp[KDIM * COUT];             // [k=(j*64+c)][o]

// packed f32x2 FMA (FFMA2) — only reachable via PTX on sm_103a
__device__ __forceinline__ float2 ffma2(float2 a, float2 b, float2 c) {
    union U { float2 f; unsigned long long u; };
    U A, B, C, D;
    A.f = a; B.f = b; C.f = c;
    asm("fma.rn.f32x2 %0, %1, %2, %3;" : "=l"(D.u) : "l"(A.u), "l"(B.u), "l"(C.u));
    return D.f;
}

// ---------------------------------------------------------------------------
// Kernel 1: transpose x[B][C][H] -> xT[H][C][B], both sides coalesced.
// grid = (CIN, ceil(H/32)), block = 256
// ---------------------------------------------------------------------------
__global__ void k_transpose(const float* __restrict__ x) {
    __shared__ float s[64][33];   // [b][hh], padded
    const int c  = blockIdx.x;
    const int h0 = blockIdx.y * 32;
    const int tid = threadIdx.x;

    // load: each warp reads one b-row of 32 contiguous h values
    for (int e = tid; e < 64 * 32; e += 256) {
        int b = e >> 5, hh = e & 31;
        int h = h0 + hh;
        float v = 0.f;
        if (h < HH) v = x[((size_t)(b * CIN + c)) * HH + h];
        s[b][hh] = v;
    }
    __syncthreads();
    // store: for fixed h, 64 consecutive b -> contiguous 256B
    for (int e = tid; e < 64 * 32; e += 256) {
        int hh = e >> 6, b = e & 63;
        int h = h0 + hh;
        if (h < HH) g_xT[((size_t)h * CIN + c) * BB + b] = s[b][hh];
    }
}

// ---------------------------------------------------------------------------
// Kernel 2: pack weights into Wp[k][o], k = j*64 + c (j=0 center, j>=1 neighbor)
// ---------------------------------------------------------------------------
__global__ void k_pack(const float* __restrict__ wc, const float* __restrict__ wn) {
    int i = blockIdx.x * 256 + threadIdx.x;
    if (i < KDIM * COUT) {
        int k = i >> 7, o = i & 127;
        int j = k >> 6, c = k & 63;
        float w = (j == 0) ? wc[o * CIN + c]
                           : wn[(o * CIN + c) * KK + (j - 1)];
        g_Wp[i] = w;
    }
}

// ---------------------------------------------------------------------------
// Kernel 3: per-h GEMM out[:, :, h] = Wp @ Xg(h), divide by count, add bias.
// grid = H, block = 256, dyn smem = Xg[448][64] f32 + Ws[64][128] float2(dup)
// Thread tile: 8 outputs (o) x 4 batch (b), FFMA2 over b-pairs.
// ---------------------------------------------------------------------------
#define SMEM_BYTES (KDIM * BB * 4 + 64 * COUT * 8)   // 114688 + 65536 = 180224

__global__ __launch_bounds__(256, 1)
void k_conv(const int* __restrict__ nbr,
            const float* __restrict__ bias,
            float* __restrict__ out) {
    extern __shared__ float smem[];
    float*  Xg = smem;                               // [448][64]
    float2* Ws = (float2*)(smem + KDIM * BB);        // [64][128] duplicated pairs

    __shared__ int   s_idx[8];
    __shared__ float s_inv;

    const int h   = blockIdx.x;
    const int tid = threadIdx.x;

    if (tid < 7) {
        s_idx[tid] = (tid == 0) ? h : nbr[h * KK + (tid - 1)];
    }
    __syncthreads();
    if (tid == 0) {
        int cnt = 1;
        #pragma unroll
        for (int j = 1; j < 7; j++) cnt += (s_idx[j] >= 0);
        s_inv = 1.0f / (float)cnt;
    }

    // Stage gathered input: 7 contiguous 16KB slabs from xT (or zeros if masked)
    #pragma unroll 1
    for (int j = 0; j < 7; j++) {
        int hj = s_idx[j];
        float4* dst = (float4*)&Xg[j * CIN * BB];
        if (hj >= 0) {
            const float4* src = (const float4*)&g_xT[(size_t)hj * CIN * BB];
            for (int e = tid; e < CIN * BB / 4; e += 256) dst[e] = src[e];
        } else {
            float4 z = make_float4(0.f, 0.f, 0.f, 0.f);
            for (int e = tid; e < CIN * BB / 4; e += 256) dst[e] = z;
        }
    }

    const int o_base = (tid >> 4) * 8;   // 16 o-groups of 8
    const int b_base = (tid & 15) * 4;   // 16 b-groups of 4

    float2 acc[8][2];
    #pragma unroll
    for (int i = 0; i < 8; i++) {
        acc[i][0] = make_float2(0.f, 0.f);
        acc[i][1] = make_float2(0.f, 0.f);
    }

    // Main loop: 7 chunks of 64 k-rows; stage Wp chunk into smem as dup pairs
    for (int kk = 0; kk < 7; kk++) {
        __syncthreads();
        const float* wsrc = &g_Wp[kk * 64 * COUT];
        for (int e = tid; e < 64 * COUT; e += 256) {
            float w = __ldg(&wsrc[e]);
            Ws[e] = make_float2(w, w);
        }
        __syncthreads();

        #pragma unroll 4
        for (int r = 0; r < 64; r++) {
            const float4 xv = *(const float4*)&Xg[(kk * 64 + r) * BB + b_base];
            float2 x01 = make_float2(xv.x, xv.y);
            float2 x23 = make_float2(xv.z, xv.w);
            const float2* wrow = &Ws[r * COUT + o_base];
            #pragma unroll
            for (int i = 0; i < 8; i++) {
                float2 wv = wrow[i];
                acc[i][0] = ffma2(wv, x01, acc[i][0]);
                acc[i][1] = ffma2(wv, x23, acc[i][1]);
            }
        }
    }

    __syncthreads();
    const float inv = s_inv;
    #pragma unroll
    for (int i = 0; i < 8; i++) {
        int o = o_base + i;
        float bo = bias[o];
        float v0 = acc[i][0].x, v1 = acc[i][0].y, v2 = acc[i][1].x, v3 = acc[i][1].y;
        out[((size_t)(b_base + 0) * COUT + o) * HH + h] = v0 * inv + bo;
        out[((size_t)(b_base + 1) * COUT + o) * HH + h] = v1 * inv + bo;
        out[((size_t)(b_base + 2) * COUT + o) * HH + h] = v2 * inv + bo;
        out[((size_t)(b_base + 3) * COUT + o) * HH + h] = v3 * inv + bo;
    }
}

// ---------------------------------------------------------------------------
extern "C" void kernel_launch(void* const* d_in, const int* in_sizes, int n_in,
                              void* d_out, int out_size) {
    const float* x    = (const float*)d_in[0];
    const int*   nbr  = (const int*)  d_in[1];
    const float* wc   = (const float*)d_in[2];
    const float* wn   = (const float*)d_in[3];
    const float* bias = (const float*)d_in[4];
    float*       out  = (float*)d_out;

    cudaFuncSetAttribute(k_conv, cudaFuncAttributeMaxDynamicSharedMemorySize,
                         SMEM_BYTES);

    k_transpose<<<dim3(CIN, (HH + 31) / 32), 256>>>(x);
    k_pack<<<(KDIM * COUT + 255) / 256, 256>>>(wc, wn);
    k_conv<<<HH, 256, SMEM_BYTES>>>(nbr, bias, out);
}

// round 7
// speedup vs baseline: 2.6865x; 2.6865x over previous
#include <cuda_runtime.h>
#include <cuda_bf16.h>
#include <cstdint>

// ---------------------------------------------------------------------------
// Problem constants
// ---------------------------------------------------------------------------
#define BB   64
#define CIN  64
#define COUT 128
#define HH   1855
#define KK   6
#define GH   2
#define NCTA ((HH + GH - 1) / GH)   // 928

// ---------------------------------------------------------------------------
// Device global scratch
//   g_X: [h][prec][b][c] bf16  (prec 0 = hi, 1 = lo), 8192 elems / h
//   g_W: [j][prec][o][c] bf16, 16384 elems / j   (j = 0 center, 1..6 neighbor)
// ---------------------------------------------------------------------------
__device__ __nv_bfloat16 g_X[(size_t)HH * 8192];   // ~30.4 MB
__device__ __nv_bfloat16 g_W[7 * 16384];
__device__ __nv_bfloat16 g_zero[8192];             // 16 KB zeros

// Padded smem rows: 64 bf16 data + 8 pad = 144 B (conflict-free ldmatrix)
#define RS     144
#define W_TILE (128 * RS)                 // 18432 B per precision
#define X_TILE (64 * RS)                  //  9216 B per precision
#define STAGE  (2 * W_TILE + GH * 2 * X_TILE)   // 73728 B
#define DSMEM  (2 * STAGE)                // 147456 B

// ---------------------------------------------------------------------------
// PTX helpers (all plain sm_80+ PTX — no 'a'-gated features)
// ---------------------------------------------------------------------------
__device__ __forceinline__ uint32_t smem_u32(const void* p) {
    uint32_t a;
    asm("{ .reg .u64 t; cvta.to.shared.u64 t, %1; cvt.u32.u64 %0, t; }"
        : "=r"(a) : "l"(p));
    return a;
}

__device__ __forceinline__ void cp16(uint32_t dst, const void* src) {
    asm volatile("cp.async.cg.shared.global [%0], [%1], 16;"
                 :: "r"(dst), "l"(src) : "memory");
}
__device__ __forceinline__ void cp_commit() {
    asm volatile("cp.async.commit_group;" ::: "memory");
}
__device__ __forceinline__ void cp_wait1() {
    asm volatile("cp.async.wait_group 1;" ::: "memory");
}
__device__ __forceinline__ void cp_wait0() {
    asm volatile("cp.async.wait_group 0;" ::: "memory");
}

__device__ __forceinline__ void ldsm4(uint32_t* r, uint32_t addr) {
    asm volatile("ldmatrix.sync.aligned.m8n8.x4.shared.b16 {%0,%1,%2,%3}, [%4];"
                 : "=r"(r[0]), "=r"(r[1]), "=r"(r[2]), "=r"(r[3]) : "r"(addr));
}

__device__ __forceinline__ void mma16816(float* c, const uint32_t* a,
                                         const uint32_t* b) {
    asm volatile(
        "mma.sync.aligned.m16n8k16.row.col.f32.bf16.bf16.f32 "
        "{%0,%1,%2,%3}, {%4,%5,%6,%7}, {%8,%9}, {%0,%1,%2,%3};"
        : "+f"(c[0]), "+f"(c[1]), "+f"(c[2]), "+f"(c[3])
        : "r"(a[0]), "r"(a[1]), "r"(a[2]), "r"(a[3]), "r"(b[0]), "r"(b[1]));
}

__device__ __forceinline__ void split_bf16(float v, unsigned short& hi,
                                           unsigned short& lo) {
    __nv_bfloat16 bh = __float2bfloat16_rn(v);
    __nv_bfloat16 bl = __float2bfloat16_rn(v - __bfloat162float(bh));
    hi = __bfloat16_as_ushort(bh);
    lo = __bfloat16_as_ushort(bl);
}

// ---------------------------------------------------------------------------
// Kernel 1: transpose + hi/lo split of x:  x[b][c][h] -> g_X[h][prec][b][c]
// grid = (64 b, 58 h-tiles), 256 threads
// ---------------------------------------------------------------------------
__global__ void k_prep(const float* __restrict__ x) {
    __shared__ float s[64][33];
    const int b   = blockIdx.x;
    const int h0  = blockIdx.y * 32;
    const int tid = threadIdx.x;

    for (int e = tid; e < 64 * 32; e += 256) {
        int c = e >> 5, hh = e & 31;
        int h = h0 + hh;
        s[c][hh] = (h < HH) ? x[((size_t)(b * CIN + c)) * HH + h] : 0.f;
    }
    __syncthreads();

    // 512 items: [prec(2)][hh(32)][oct(8)], each a uint4 (8 bf16)
    for (int e = tid; e < 512; e += 256) {
        int prec = e >> 8, idx = e & 255;
        int hh = idx >> 3, oct = idx & 7;
        int h = h0 + hh;
        if (h >= HH) continue;
        unsigned int r[4];
        #pragma unroll
        for (int p = 0; p < 4; p++) {
            unsigned short h0b, l0b, h1b, l1b;
            split_bf16(s[oct * 8 + 2 * p + 0][hh], h0b, l0b);
            split_bf16(s[oct * 8 + 2 * p + 1][hh], h1b, l1b);
            unsigned short u0 = prec ? l0b : h0b;
            unsigned short u1 = prec ? l1b : h1b;
            r[p] = (unsigned)u0 | ((unsigned)u1 << 16);
        }
        size_t off = (size_t)h * 8192 + prec * 4096 + b * 64 + oct * 8;
        *(uint4*)((char*)g_X + off * 2) = make_uint4(r[0], r[1], r[2], r[3]);
    }
}

// ---------------------------------------------------------------------------
// Kernel 2: pack + split weights -> g_W[j][prec][o][c]
// ---------------------------------------------------------------------------
__global__ void k_packW(const float* __restrict__ wc, const float* __restrict__ wn) {
    int i = blockIdx.x * 256 + threadIdx.x;   // 7*128*64 = 57344
    if (i < 7 * COUT * CIN) {
        int j = i >> 13;                // / 8192
        int o = (i >> 6) & 127;
        int c = i & 63;
        float w = (j == 0) ? wc[o * CIN + c] : wn[(o * CIN + c) * KK + (j - 1)];
        unsigned short uh, ul;
        split_bf16(w, uh, ul);
        g_W[(size_t)j * 16384 +        o * 64 + c] = __ushort_as_bfloat16(uh);
        g_W[(size_t)j * 16384 + 8192 + o * 64 + c] = __ushort_as_bfloat16(ul);
    }
}

__global__ void k_zero() {
    int i = blockIdx.x * 1024 + threadIdx.x;
    if (i < 8192) g_zero[i] = __float2bfloat16(0.f);
}

// ---------------------------------------------------------------------------
// Kernel 3: HMMA conv.  CTA = 2 hexagons, 256 threads = 8 warps (2o x 2b x 2h).
// Per h:  D[o=128, b=64] = sum_j W_j[o, 64c] * X_{n(h,j)}[b, 64c]^T
// 3-term split bf16: Ah*Bh + Ah*Bl + Al*Bh, fp32 accum in registers.
// Double-buffered cp.async pipeline over the 7 K-chunks.
// ---------------------------------------------------------------------------
__global__ __launch_bounds__(256, 1)
void k_conv(const int* __restrict__ nbr, const float* __restrict__ bias,
            float* __restrict__ out) {
    extern __shared__ char dsm[];
    const uint32_t base = smem_u32(dsm);

    __shared__ int   s_sidx[GH][7];
    __shared__ float s_inv[GH];
    __shared__ float s_bias[COUT];

    const int tid  = threadIdx.x;
    const int lane = tid & 31;
    const int wid  = tid >> 5;
    const int wo = wid >> 2;          // o-tile: 64 rows
    const int wb = (wid >> 1) & 1;    // b-tile: 32 cols
    const int wh = wid & 1;           // hexagon within pair
    const int h0 = blockIdx.x * GH;

    if (tid < GH * 7) {
        int hh = tid / 7, j = tid % 7;
        int v = -1;
        int h = h0 + hh;
        if (h < HH) v = (j == 0) ? h : nbr[h * KK + (j - 1)];
        s_sidx[hh][j] = v;
    }
    if (tid < COUT) s_bias[tid] = bias[tid];
    __syncthreads();
    if (tid < GH) {
        int cnt = 1;
        #pragma unroll
        for (int j = 1; j < 7; j++) cnt += (s_sidx[tid][j] >= 0);
        s_inv[tid] = 1.0f / (float)cnt;
    }
    __syncthreads();

    // ---- cp.async stage issue: W (2048 chunks) + X (2048 chunks) of 16B ----
    auto issue_stage = [&](int j, int s) {
        const uint32_t sb = base + s * STAGE;
        const char* wsrc = (const char*)g_W + (size_t)j * 32768;
        for (int i = tid; i < 2048; i += 256) {
            int prec = i >> 10, rem = i & 1023;
            int row = rem >> 3, oct = rem & 7;
            cp16(sb + prec * W_TILE + row * RS + oct * 16,
                 wsrc + prec * 16384 + row * 128 + oct * 16);
        }
        for (int i = tid; i < 2048; i += 256) {
            int h    = i >> 10;
            int prec = (i >> 9) & 1;
            int row  = (i >> 3) & 63;
            int oct  = i & 7;
            int hv   = s_sidx[h][j];
            const char* xsrc = (hv >= 0)
                ? (const char*)g_X + (size_t)hv * 16384
                : (const char*)g_zero;
            cp16(sb + 2 * W_TILE + h * (2 * X_TILE) + prec * X_TILE + row * RS + oct * 16,
                 xsrc + prec * 8192 + row * 128 + oct * 16);
        }
        cp_commit();
    };

    issue_stage(0, 0);
    issue_stage(1, 1);

    // ---- fragment address offsets (within tile) ----
    const uint32_t aoff = (uint32_t)(wo * 64 + (lane & 15)) * RS + (lane >> 4) * 16;
    const uint32_t boff = (uint32_t)(wb * 32 + (lane & 7) + (lane >> 4) * 8) * RS
                        + ((lane >> 3) & 1) * 16;

    float acc[4][4][4];
    #pragma unroll
    for (int mi = 0; mi < 4; mi++)
        #pragma unroll
        for (int ni = 0; ni < 4; ni++)
            #pragma unroll
            for (int c = 0; c < 4; c++) acc[mi][ni][c] = 0.f;

    for (int j = 0; j < 7; j++) {
        const int s = j & 1;
        if (j == 6) cp_wait0(); else cp_wait1();
        __syncthreads();

        const uint32_t Wb  = base + s * STAGE;
        const uint32_t WbL = Wb + W_TILE;
        const uint32_t Xb  = Wb + 2 * W_TILE + wh * (2 * X_TILE);
        const uint32_t XbL = Xb + X_TILE;

        #pragma unroll 2
        for (int ks = 0; ks < 4; ks++) {
            const uint32_t kb = ks * 32;
            uint32_t ah[4][4], al[4][4], bh[2][4], bl[2][4];
            #pragma unroll
            for (int mi = 0; mi < 4; mi++) {
                ldsm4(ah[mi], Wb  + aoff + mi * 16 * RS + kb);
                ldsm4(al[mi], WbL + aoff + mi * 16 * RS + kb);
            }
            ldsm4(bh[0], Xb  + boff + kb);
            ldsm4(bh[1], Xb  + boff + 16 * RS + kb);
            ldsm4(bl[0], XbL + boff + kb);
            ldsm4(bl[1], XbL + boff + 16 * RS + kb);

            #pragma unroll
            for (int mi = 0; mi < 4; mi++)
                #pragma unroll
                for (int ni = 0; ni < 4; ni++) {
                    const uint32_t* Bh = &bh[ni >> 1][(ni & 1) * 2];
                    const uint32_t* Bl = &bl[ni >> 1][(ni & 1) * 2];
                    mma16816(acc[mi][ni], ah[mi], Bh);
                    mma16816(acc[mi][ni], ah[mi], Bl);
                    mma16816(acc[mi][ni], al[mi], Bh);
                }
        }
        __syncthreads();                  // all reads of buffer s done
        if (j + 2 <= 6) issue_stage(j + 2, s);
    }

    // ---- epilogue: scale + bias, transpose through smem, h-paired stores ----
    __syncthreads();
    float* SF = (float*)dsm + (size_t)wh * (64 * 132);   // [b][o], o-stride 132
    const float inv = s_inv[wh];
    #pragma unroll
    for (int mi = 0; mi < 4; mi++)
        #pragma unroll
        for (int ni = 0; ni < 4; ni++)
            #pragma unroll
            for (int c = 0; c < 4; c++) {
                int o = wo * 64 + mi * 16 + (lane >> 2) + ((c & 2) ? 8 : 0);
                int b = wb * 32 + ni * 8 + (lane & 3) * 2 + (c & 1);
                SF[b * 132 + o] = acc[mi][ni][c] * inv + s_bias[o];
            }
    __syncthreads();

    float* S0 = (float*)dsm;
    const bool has2 = (h0 + 1) < HH;
    for (int i = tid; i < BB * COUT; i += 256) {
        int b = i >> 7, o = i & 127;
        size_t addr = ((size_t)(b * COUT + o)) * HH + h0;
        out[addr] = S0[b * 132 + o];
        if (has2) out[addr + 1] = S0[64 * 132 + b * 132 + o];
    }
}

// ---------------------------------------------------------------------------
extern "C" void kernel_launch(void* const* d_in, const int* in_sizes, int n_in,
                              void* d_out, int out_size) {
    const float* x    = (const float*)d_in[0];
    const int*   nbr  = (const int*)  d_in[1];
    const float* wc   = (const float*)d_in[2];
    const float* wn   = (const float*)d_in[3];
    const float* bias = (const float*)d_in[4];
    float*       out  = (float*)d_out;

    cudaFuncSetAttribute(k_conv, cudaFuncAttributeMaxDynamicSharedMemorySize,
                         DSMEM);

    k_prep <<<dim3(64, (HH + 31) / 32), 256>>>(x);
    k_packW<<<(7 * COUT * CIN + 255) / 256, 256>>>(wc, wn);
    k_zero <<<8, 1024>>>();
    k_conv <<<NCTA, 256, DSMEM>>>(nbr, bias, out);
}